// round 13
// baseline (speedup 1.0000x reference)
#include <cuda_runtime.h>
#include <math.h>

// Problem constants (fixed by the bench problem)
#define AA     48          // atoms per batch
#define SS     4           // num species
#define NR     16          // num radial shifts
#define NAA    4           // num angular radial shifts
#define NZ     8           // num angular shifts
#define NPAIRS (SS*(SS+1)/2)   // 10
#define RADD   (SS*NR)         // 64
#define ANGD   (NPAIRS*NAA*NZ) // 320
#define OUTD   (RADD+ANGD)     // 384
#define RCR    5.2f
#define RCA    3.5f
#define PI_F   3.14159265358979323846f
#define NTHR   704             // 20 angular warps + 2 radial warps

__global__ __launch_bounds__(NTHR) void aev_kernel(
    const int*   __restrict__ species,   // [B, A]
    const float* __restrict__ coords,    // [B, A, 3]
    const float* __restrict__ EtaR,      // [1]
    const float* __restrict__ ShfR,      // [NR]
    const float* __restrict__ EtaA,      // [1]
    const float* __restrict__ Zeta,      // [1]
    const float* __restrict__ ShfA,      // [NAA]
    const float* __restrict__ ShfZ,      // [NZ]
    float*       __restrict__ out)       // [B, A, OUTD]
{
    // species-bucketed neighbor lists (bucket s at base s*AA)
    __shared__ float4 abuc[SS*AA];      // angular: dx,dy,dz,d
    __shared__ float2 afcb[SS*AA];      // angular: fc, 1/d
    __shared__ float2 rbuc[SS*AA];      // radial:  d, fc
    __shared__ int    cntA[SS], cntR[SS];
    __shared__ float  partial[NPAIRS*32];   // half=1 warps' partial sums

    const int tid  = threadIdx.x;
    const int wid  = tid >> 5;
    const int lane = tid & 31;
    const int aidx = blockIdx.x;
    const int i    = aidx % AA;
    const int b    = aidx / AA;

    // ---- params -> registers ----
    const float etaR = EtaR[0];
    const float etaA = EtaA[0];
    const float zeta = Zeta[0];
    const float shfr = ShfR[tid & 15];          // radial feature param
    const float shfa = ShfA[lane >> 3];         // angular feature (a,z)
    const float shz  = ShfZ[lane & 7];
    const float cz   = __cosf(shz);
    const float sz   = __sinf(shz);

    // counters zeroed by threads outside the 0..47 distance group
    if (tid >= 64 && tid < 64 + SS) cntA[tid - 64] = 0;
    if (tid >= 96 && tid < 96 + SS) cntR[tid - 96] = 0;

    // ---- distances in registers (threads 0..47) ----
    float dxr=0, dyr=0, dzr=0, drr=0, fcrv=0, fcav=0, invd=0;
    bool  pvR=false, pvA=false;
    int   spj=0;
    if (tid < AA) {
        int j = tid;
        const float* cb = coords + (size_t)b*AA*3;
        float xi = cb[3*i], yi = cb[3*i+1], zi = cb[3*i+2];
        float dx = xi - cb[3*j], dy = yi - cb[3*j+1], dz = zi - cb[3*j+2];
        float d  = sqrtf(dx*dx + dy*dy + dz*dz);
        spj = species[b*AA + j];
        int spi = species[b*AA + i];
        bool pv = (spi >= 0) && (spj >= 0) && (j != i);
        dxr = dx; dyr = dy; dzr = dz; drr = d;
        pvR = pv && (d <= RCR);
        pvA = pv && (d <= RCA);
        fcrv = 0.5f*__cosf(PI_F * d * (1.0f/RCR)) + 0.5f;
        fcav = 0.5f*__cosf(PI_F * d * (1.0f/RCA)) + 0.5f;
        invd = __frcp_rn(fmaxf(d, 1e-4f));
    }
    __syncthreads();   // #1: counters ready

    // ---- bucketed compaction ----
    if (tid < AA) {
        if (pvR) {
            int s = atomicAdd(&cntR[spj], 1);
            rbuc[spj*AA + s] = make_float2(drr, fcrv);
        }
        if (pvA) {
            int s = atomicAdd(&cntA[spj], 1);
            abuc[spj*AA + s] = make_float4(dxr, dyr, dzr, drr);
            afcb[spj*AA + s] = make_float2(fcav, invd);
        }
    }
    __syncthreads();   // #2: buckets ready

    float* o = out + (size_t)aidx * OUTD;
    float acc = 0.0f;
    int   cls = 0;

    if (wid < 20) {
        // ===== ANGULAR: 2 warps per pair-class, lane = (a,z) feature =====
        cls = wid >> 1;
        const int half = wid & 1;
        const int lo    = (cls < 4) ? 0 : (cls < 7) ? 1 : (cls < 9) ? 2 : 3;
        const int basew = (cls < 4) ? 0 : (cls < 7) ? 4 : (cls < 9) ? 7 : 9;
        const int hi    = lo + (cls - basew);
        const int nLo = cntA[lo], nHi = cntA[hi];
        const int bLo = lo*AA, bHi = hi*AA;

        if (lo == hi) {
            for (int p = half; p < nLo - 1; p += 2) {
                float4 P  = abuc[bLo + p];
                float2 Fp = afcb[bLo + p];
                for (int q = p + 1; q < nLo; q++) {
                    float4 Q  = abuc[bLo + q];
                    float2 Fq = afcb[bLo + q];
                    float dot  = P.x*Q.x + P.y*Q.y + P.z*Q.z;
                    float cosA = 0.95f * dot * Fp.y * Fq.y;
                    float sinA = sqrtf(fmaxf(1.0f - cosA*cosA, 0.0f));
                    float t    = 0.5f*(P.w + Q.w) - shfa;
                    float f2   = 2.0f * Fp.x * Fq.x * __expf(-etaA * t * t);
                    float x    = 0.5f + 0.5f*(cosA*cz + sinA*sz);
                    float f1;
                    if (zeta == 32.0f) {
                        float x2 = x*x, x4 = x2*x2, x8 = x4*x4, x16 = x8*x8;
                        f1 = x16*x16;
                    } else {
                        f1 = __powf(x, zeta);
                    }
                    acc += f1 * f2;
                }
            }
        } else {
            for (int p = half; p < nLo; p += 2) {
                float4 P  = abuc[bLo + p];
                float2 Fp = afcb[bLo + p];
                for (int q = 0; q < nHi; q++) {
                    float4 Q  = abuc[bHi + q];
                    float2 Fq = afcb[bHi + q];
                    float dot  = P.x*Q.x + P.y*Q.y + P.z*Q.z;
                    float cosA = 0.95f * dot * Fp.y * Fq.y;
                    float sinA = sqrtf(fmaxf(1.0f - cosA*cosA, 0.0f));
                    float t    = 0.5f*(P.w + Q.w) - shfa;
                    float f2   = 2.0f * Fp.x * Fq.x * __expf(-etaA * t * t);
                    float x    = 0.5f + 0.5f*(cosA*cz + sinA*sz);
                    float f1;
                    if (zeta == 32.0f) {
                        float x2 = x*x, x4 = x2*x2, x8 = x4*x4, x16 = x8*x8;
                        f1 = x16*x16;
                    } else {
                        f1 = __powf(x, zeta);
                    }
                    acc += f1 * f2;
                }
            }
        }
        if (half) partial[cls*32 + lane] = acc;
    } else {
        // ===== RADIAL: thread = (s,r) feature, loops over bucket s only =====
        const int tr = tid - 640;           // 0..63
        const int s  = tr >> 4;
        const int n  = cntR[s];
        const int bs = s*AA;
        float ra = 0.0f;
        for (int k = 0; k < n; k++) {
            float2 v  = rbuc[bs + k];
            float  dd = v.x - shfr;
            ra += __expf(-etaR * dd * dd) * v.y;
        }
        o[tr] = 0.25f * ra;
    }
    __syncthreads();   // #3: partials ready

    // half=0 warps combine and store (one coalesced 128B STG per class)
    if (wid < 20 && !(wid & 1)) {
        o[RADD + cls*32 + lane] = acc + partial[cls*32 + lane];
    }
}

extern "C" void kernel_launch(void* const* d_in, const int* in_sizes, int n_in,
                              void* d_out, int out_size)
{
    const int*   species = (const int*)  d_in[0];
    const float* coords  = (const float*)d_in[1];
    const float* EtaR    = (const float*)d_in[2];
    const float* ShfR    = (const float*)d_in[3];
    const float* EtaA    = (const float*)d_in[4];
    const float* Zeta    = (const float*)d_in[5];
    const float* ShfA    = (const float*)d_in[6];
    const float* ShfZ    = (const float*)d_in[7];
    float* out = (float*)d_out;

    int B = in_sizes[0] / AA;   // species is [B, A]
    aev_kernel<<<B * AA, NTHR>>>(species, coords, EtaR, ShfR, EtaA, Zeta,
                                 ShfA, ShfZ, out);
}

// round 14
// speedup vs baseline: 1.1232x; 1.1232x over previous
#include <cuda_runtime.h>
#include <math.h>

// Problem constants (fixed by the bench problem)
#define AA     48          // atoms per batch
#define SS     4           // num species
#define NR     16          // num radial shifts
#define NAA    4           // num angular radial shifts
#define NZ     8           // num angular shifts
#define NPAIRS (SS*(SS+1)/2)   // 10
#define RADD   (SS*NR)         // 64
#define ANGD   (NPAIRS*NAA*NZ) // 320
#define OUTD   (RADD+ANGD)     // 384
#define RCR    5.2f
#define RCA    3.5f
#define PI_F   3.14159265358979323846f

// per-pair angular feature value; P/Q hold unit vector (x,y,z) and distance (w)
__device__ __forceinline__ float pair_term(
    float4 P, float fcp, float4 Q, float fcq,
    float shfa, float cz, float sz, float etaA, float zeta)
{
    float cosA = 0.95f * (P.x*Q.x + P.y*Q.y + P.z*Q.z);
    float sinA = sqrtf(fmaxf(1.0f - cosA*cosA, 0.0f));
    float t    = 0.5f*(P.w + Q.w) - shfa;
    float f2   = 2.0f * fcp * fcq * __expf(-etaA * t * t);
    float x    = 0.5f + 0.5f*(cosA*cz + sinA*sz);
    float f1;
    if (zeta == 32.0f) {
        float x2 = x*x, x4 = x2*x2, x8 = x4*x4, x16 = x8*x8;
        f1 = x16*x16;
    } else {
        f1 = __powf(x, zeta);
    }
    return f1 * f2;
}

__global__ __launch_bounds__(384) void aev_kernel(
    const int*   __restrict__ species,   // [B, A]
    const float* __restrict__ coords,    // [B, A, 3]
    const float* __restrict__ EtaR,      // [1]
    const float* __restrict__ ShfR,      // [NR]
    const float* __restrict__ EtaA,      // [1]
    const float* __restrict__ Zeta,      // [1]
    const float* __restrict__ ShfA,      // [NAA]
    const float* __restrict__ ShfZ,      // [NZ]
    float*       __restrict__ out)       // [B, A, OUTD]
{
    // species-bucketed neighbor lists (bucket s at base s*AA)
    __shared__ float4 abuc[SS*AA];      // angular: unit dx,dy,dz, d
    __shared__ float  afcb[SS*AA];      // angular: fc
    __shared__ float2 rbuc[SS*AA];      // radial:  d, fc
    __shared__ int    cntA[SS], cntR[SS];

    const int tid  = threadIdx.x;
    const int wid  = tid >> 5;
    const int lane = tid & 31;
    const int aidx = blockIdx.x;
    const int i    = aidx % AA;
    const int b    = aidx / AA;

    // ---- params -> registers (independent LDGs, overlap prologue) ----
    const float etaR = EtaR[0];
    const float etaA = EtaA[0];
    const float zeta = Zeta[0];
    const float shfr = ShfR[tid & 15];          // radial feature param
    const float shfa = ShfA[lane >> 3];         // angular feature (a,z)
    const float shz  = ShfZ[lane & 7];
    const float cz   = __cosf(shz);
    const float sz   = __sinf(shz);

    // counters zeroed by threads outside the 0..47 distance group
    if (tid >= 64 && tid < 64 + SS) cntA[tid - 64] = 0;
    if (tid >= 96 && tid < 96 + SS) cntR[tid - 96] = 0;

    // ---- distances in registers (threads 0..47) ----
    float uxr=0, uyr=0, uzr=0, drr=0, fcrv=0, fcav=0;
    bool  pvR=false, pvA=false;
    int   spj=0;
    if (tid < AA) {
        int j = tid;
        const float* cb = coords + (size_t)b*AA*3;
        float xi = cb[3*i], yi = cb[3*i+1], zi = cb[3*i+2];
        float dx = xi - cb[3*j], dy = yi - cb[3*j+1], dz = zi - cb[3*j+2];
        float d2 = dx*dx + dy*dy + dz*dz;
        float d  = sqrtf(d2);
        spj = species[b*AA + j];
        int spi = species[b*AA + i];
        bool pv = (spi >= 0) && (spj >= 0) && (j != i);
        drr = d;
        pvR = pv && (d <= RCR);
        pvA = pv && (d <= RCA);
        fcrv = 0.5f*__cosf(PI_F * d * (1.0f/RCR)) + 0.5f;
        fcav = 0.5f*__cosf(PI_F * d * (1.0f/RCA)) + 0.5f;
        float invd = __frsqrt_rn(fmaxf(d2, 1e-12f));
        uxr = dx*invd; uyr = dy*invd; uzr = dz*invd;
    }
    __syncthreads();   // #1: counters ready

    // ---- bucketed compaction ----
    if (tid < AA) {
        if (pvR) {
            int s = atomicAdd(&cntR[spj], 1);
            rbuc[spj*AA + s] = make_float2(drr, fcrv);
        }
        if (pvA) {
            int s = atomicAdd(&cntA[spj], 1);
            abuc[spj*AA + s] = make_float4(uxr, uyr, uzr, drr);
            afcb[spj*AA + s] = fcav;
        }
    }
    __syncthreads();   // #2: buckets ready

    float* o = out + (size_t)aidx * OUTD;

    if (wid < NPAIRS) {
        // ===== ANGULAR: warp = pair-class (lo,hi), lane = (a,z) feature =====
        const int lo    = (wid < 4) ? 0 : (wid < 7) ? 1 : (wid < 9) ? 2 : 3;
        const int basew = (wid < 4) ? 0 : (wid < 7) ? 4 : (wid < 9) ? 7 : 9;
        const int hi    = lo + (wid - basew);
        const int nLo = cntA[lo], nHi = cntA[hi];
        const int bLo = lo*AA, bHi = hi*AA;
        float acc0 = 0.0f, acc1 = 0.0f;   // dual chains for ILP

        if (lo == hi) {
            for (int p = 0; p < nLo - 1; p++) {
                float4 P  = abuc[bLo + p];
                float fcp = afcb[bLo + p];
                int q = p + 1;
                for (; q + 1 < nLo; q += 2) {
                    float4 Q0  = abuc[bLo + q];
                    float fcq0 = afcb[bLo + q];
                    float4 Q1  = abuc[bLo + q + 1];
                    float fcq1 = afcb[bLo + q + 1];
                    acc0 += pair_term(P, fcp, Q0, fcq0, shfa, cz, sz, etaA, zeta);
                    acc1 += pair_term(P, fcp, Q1, fcq1, shfa, cz, sz, etaA, zeta);
                }
                if (q < nLo) {
                    float4 Q  = abuc[bLo + q];
                    float fcq = afcb[bLo + q];
                    acc0 += pair_term(P, fcp, Q, fcq, shfa, cz, sz, etaA, zeta);
                }
            }
        } else {
            for (int p = 0; p < nLo; p++) {
                float4 P  = abuc[bLo + p];
                float fcp = afcb[bLo + p];
                int q = 0;
                for (; q + 1 < nHi; q += 2) {
                    float4 Q0  = abuc[bHi + q];
                    float fcq0 = afcb[bHi + q];
                    float4 Q1  = abuc[bHi + q + 1];
                    float fcq1 = afcb[bHi + q + 1];
                    acc0 += pair_term(P, fcp, Q0, fcq0, shfa, cz, sz, etaA, zeta);
                    acc1 += pair_term(P, fcp, Q1, fcq1, shfa, cz, sz, etaA, zeta);
                }
                if (q < nHi) {
                    float4 Q  = abuc[bHi + q];
                    float fcq = afcb[bHi + q];
                    acc0 += pair_term(P, fcp, Q, fcq, shfa, cz, sz, etaA, zeta);
                }
            }
        }
        o[RADD + wid*32 + lane] = acc0 + acc1;
    } else {
        // ===== RADIAL: thread = (s,r) feature, loops over bucket s only =====
        const int tr = tid - NPAIRS*32;     // 0..63
        const int s  = tr >> 4;
        const int n  = cntR[s];
        const int bs = s*AA;
        float ra0 = 0.0f, ra1 = 0.0f;
        int k = 0;
        for (; k + 1 < n; k += 2) {
            float2 v0 = rbuc[bs + k];
            float2 v1 = rbuc[bs + k + 1];
            float dd0 = v0.x - shfr;
            float dd1 = v1.x - shfr;
            ra0 += __expf(-etaR * dd0 * dd0) * v0.y;
            ra1 += __expf(-etaR * dd1 * dd1) * v1.y;
        }
        if (k < n) {
            float2 v  = rbuc[bs + k];
            float dd  = v.x - shfr;
            ra0 += __expf(-etaR * dd * dd) * v.y;
        }
        o[tr] = 0.25f * (ra0 + ra1);
    }
}

extern "C" void kernel_launch(void* const* d_in, const int* in_sizes, int n_in,
                              void* d_out, int out_size)
{
    const int*   species = (const int*)  d_in[0];
    const float* coords  = (const float*)d_in[1];
    const float* EtaR    = (const float*)d_in[2];
    const float* ShfR    = (const float*)d_in[3];
    const float* EtaA    = (const float*)d_in[4];
    const float* Zeta    = (const float*)d_in[5];
    const float* ShfA    = (const float*)d_in[6];
    const float* ShfZ    = (const float*)d_in[7];
    float* out = (float*)d_out;

    int B = in_sizes[0] / AA;   // species is [B, A]
    aev_kernel<<<B * AA, 384>>>(species, coords, EtaR, ShfR, EtaA, Zeta,
                                ShfA, ShfZ, out);
}